// round 3
// baseline (speedup 1.0000x reference)
#include <cuda_runtime.h>
#include <math.h>

#define THREADS 256
#define ROWS 64
#define KC 32
#define LDA 36       // activation smem ld (32+4): (4*l4+lm)%32 distinct -> conflict-free
#define LDP 132      // P smem ld (128+4)

// smem float offsets
#define OFF_ACT 0        // 2 x 64x36 = 4608
#define OFF_WK  4608     // 2 x 4096 = 8192
#define OFF_WV  12800    // 2 x 4096 = 8192  (ends 20992)
#define OFF_WO  0        // phase C Wo frag buffer: 16384 (overlays ACT+WK+part WV)
#define OFF_QS  20992    // P: 64x132 = 8448
#define OFF_BO  29440    // 512
#define OFF_G   29952    // 512
#define OFF_N2  30464    // 64
#define OFF_RS  30528    // 64
#define SMEM_FLOATS 30592

__device__ __forceinline__ unsigned tf32_bits(float x) {
    unsigned u; asm("cvt.rna.tf32.f32 %0, %1;" : "=r"(u) : "f"(x)); return u;
}
__device__ __forceinline__ float tf32f(float x) { return __uint_as_float(tf32_bits(x)); }

__device__ __forceinline__ void mma8(float* d, unsigned a0, unsigned a1, unsigned a2, unsigned a3,
                                     unsigned b0, unsigned b1) {
    asm volatile(
        "mma.sync.aligned.m16n8k8.row.col.f32.tf32.tf32.f32 "
        "{%0,%1,%2,%3},{%4,%5,%6,%7},{%8,%9},{%0,%1,%2,%3};"
        : "+f"(d[0]), "+f"(d[1]), "+f"(d[2]), "+f"(d[3])
        : "r"(a0), "r"(a1), "r"(a2), "r"(a3), "r"(b0), "r"(b1));
}

#define CP_COMMIT() asm volatile("cp.async.commit_group;")
#define CP_WAIT0()  asm volatile("cp.async.wait_group 0;")

// activations: 64 rows x 32 cols -> smem [r*LDA + c] via cp.async 16B (512 float4, 2/thread)
__device__ __forceinline__ void act_cp(float* sm, int dstBase, const float* A,
                                       size_t rowBase, int gld, int kb, int tid) {
#pragma unroll
    for (int i = 0; i < 2; i++) {
        const int idx = tid + THREADS * i;
        const int r = idx >> 3, q = (idx & 7) * 4;
        unsigned sa = (unsigned)__cvta_generic_to_shared(&sm[dstBase + r * LDA + q]);
        const float* gp = A + (rowBase + r) * (size_t)gld + kb + q;
        asm volatile("cp.async.cg.shared.global [%0], [%1], 16;" :: "r"(sa), "l"(gp));
    }
}

// fragment-major weight prefetch: tile T (cols T*8..T*8+7), lane (l4,lm)
// a-half: k = lm + {0,4,8,12}; b-half: k = 16 + lm + {0,4,8,12}   (gmem W is [K,128] row-major)
__device__ __forceinline__ void wldg(const float* W, int kb, int T, int lane, float r[8]) {
    const int l4 = lane >> 2, lm = lane & 3;
    const float* p = W + (size_t)(kb + lm) * 128 + T * 8 + l4;
    r[0] = __ldg(p);            r[1] = __ldg(p + 4 * 128);
    r[2] = __ldg(p + 8 * 128);  r[3] = __ldg(p + 12 * 128);
    r[4] = __ldg(p + 16 * 128); r[5] = __ldg(p + 20 * 128);
    r[6] = __ldg(p + 24 * 128); r[7] = __ldg(p + 28 * 128);
}
// store frag-major: WF[T][lane][4] (a-half at +0, b-half at +2048); STS.128 conflict-free
__device__ __forceinline__ void wsts(float* base, int T, int lane, const float r[8]) {
    float4 a = make_float4(tf32f(r[0]), tf32f(r[1]), tf32f(r[2]), tf32f(r[3]));
    float4 b = make_float4(tf32f(r[4]), tf32f(r[5]), tf32f(r[6]), tf32f(r[7]));
    *(float4*)&base[T * 128 + lane * 4] = a;
    *(float4*)&base[2048 + T * 128 + lane * 4] = b;
}

__global__ void __launch_bounds__(THREADS, 1)
lca_tc(const float* __restrict__ x,  const float* __restrict__ ctx,
       const float* __restrict__ Wq, const float* __restrict__ Wk,
       const float* __restrict__ Wv, const float* __restrict__ Wo,
       const float* __restrict__ bo, const float* __restrict__ g,
       float* __restrict__ out)
{
    extern __shared__ float sm[];
    const int tid  = threadIdx.x;
    const int lane = tid & 31;
    const int warp = tid >> 5;
    const int l4   = lane >> 2;
    const int lm   = lane & 3;
    const int band = warp >> 2;      // 0/1 -> rows band*32 .. +31
    const int colgrp = warp & 3;     // phases A/B: cols colgrp*32; phase C: colgrp*128
    const size_t Rbase = (size_t)blockIdx.x * ROWS;

    // preload bo, g; zero norm accumulators (visible by first __syncthreads)
    for (int i = tid; i < 512; i += THREADS) {
        sm[OFF_BO + i] = __ldg(&bo[i]);
        sm[OFF_G + i]  = __ldg(&g[i]);
    }
    if (tid < 64) sm[OFF_N2 + tid] = 0.f;

    float qa[2][4][4];
#pragma unroll
    for (int m = 0; m < 2; m++)
#pragma unroll
        for (int t = 0; t < 4; t++)
#pragma unroll
            for (int j = 0; j < 4; j++) qa[m][t][j] = 0.f;

    // ======================= Phase A: Q = x @ Wq =======================
    {
        float w1[8], w2[8];
        wldg(Wq, 0, warp, lane, w1); wldg(Wq, 0, warp + 8, lane, w2);
        wsts(&sm[OFF_WK], warp, lane, w1); wsts(&sm[OFF_WK], warp + 8, lane, w2);
        act_cp(sm, OFF_ACT, x, Rbase, 512, 0, tid);
        CP_COMMIT();

#pragma unroll 1
        for (int c = 0; c < 16; c++) {
            const int cb = c & 1;
            if (c + 1 < 16) { wldg(Wq, (c + 1) * KC, warp, lane, w1);
                              wldg(Wq, (c + 1) * KC, warp + 8, lane, w2); }
            CP_WAIT0();
            __syncthreads();
            if (c + 1 < 16) { act_cp(sm, OFF_ACT + (cb ^ 1) * 2304, x, Rbase, 512, (c + 1) * KC, tid);
                              CP_COMMIT(); }
            const float* AB = &sm[OFF_ACT + cb * 2304];
            const float* WB = &sm[OFF_WK + cb * 4096];
#pragma unroll
            for (int hf = 0; hf < 2; hf++) {
                float4 Bt[4];
#pragma unroll
                for (int t = 0; t < 4; t++)
                    Bt[t] = *(const float4*)&WB[hf * 2048 + (colgrp * 4 + t) * 128 + lane * 4];
#pragma unroll
                for (int ks2 = 0; ks2 < 2; ks2++) {
                    const int k = hf * 16 + ks2 * 8 + lm;
                    unsigned a0[2], a1[2], a2[2], a3[2];
#pragma unroll
                    for (int m = 0; m < 2; m++) {
                        const float* Ap = &AB[(band * 32 + m * 16 + l4) * LDA + k];
                        a0[m] = tf32_bits(Ap[0]);       a1[m] = tf32_bits(Ap[8 * LDA]);
                        a2[m] = tf32_bits(Ap[4]);       a3[m] = tf32_bits(Ap[8 * LDA + 4]);
                    }
#pragma unroll
                    for (int t = 0; t < 4; t++) {
                        const unsigned b0 = __float_as_uint(ks2 ? Bt[t].z : Bt[t].x);
                        const unsigned b1 = __float_as_uint(ks2 ? Bt[t].w : Bt[t].y);
                        mma8(qa[0][t], a0[0], a1[0], a2[0], a3[0], b0, b1);
                        mma8(qa[1][t], a0[1], a1[1], a2[1], a3[1], b0, b1);
                    }
                }
            }
            if (c + 1 < 16) { wsts(&sm[OFF_WK + (cb ^ 1) * 4096], warp, lane, w1);
                              wsts(&sm[OFF_WK + (cb ^ 1) * 4096], warp + 8, lane, w2); }
        }
    }

    // ============ softmax over head dim, in registers (head = colgrp) ============
    {
        const float SCL = 0.17677669529663687f;  // 32^-0.5
#pragma unroll
        for (int m = 0; m < 2; m++) {
            float mxA = -1e30f, mxB = -1e30f;
#pragma unroll
            for (int t = 0; t < 4; t++) {
                mxA = fmaxf(mxA, fmaxf(qa[m][t][0], qa[m][t][1]));
                mxB = fmaxf(mxB, fmaxf(qa[m][t][2], qa[m][t][3]));
            }
            mxA = fmaxf(mxA, __shfl_xor_sync(0xffffffffu, mxA, 1));
            mxA = fmaxf(mxA, __shfl_xor_sync(0xffffffffu, mxA, 2));
            mxB = fmaxf(mxB, __shfl_xor_sync(0xffffffffu, mxB, 1));
            mxB = fmaxf(mxB, __shfl_xor_sync(0xffffffffu, mxB, 2));
            float sA = 0.f, sB = 0.f;
#pragma unroll
            for (int t = 0; t < 4; t++) {
                qa[m][t][0] = __expf(qa[m][t][0] - mxA); sA += qa[m][t][0];
                qa[m][t][1] = __expf(qa[m][t][1] - mxA); sA += qa[m][t][1];
                qa[m][t][2] = __expf(qa[m][t][2] - mxB); sB += qa[m][t][2];
                qa[m][t][3] = __expf(qa[m][t][3] - mxB); sB += qa[m][t][3];
            }
            sA += __shfl_xor_sync(0xffffffffu, sA, 1);
            sA += __shfl_xor_sync(0xffffffffu, sA, 2);
            sB += __shfl_xor_sync(0xffffffffu, sB, 1);
            sB += __shfl_xor_sync(0xffffffffu, sB, 2);
            const float iA = SCL / sA, iB = SCL / sB;
#pragma unroll
            for (int t = 0; t < 4; t++) {
                qa[m][t][0] *= iA; qa[m][t][1] *= iA;
                qa[m][t][2] *= iB; qa[m][t][3] *= iB;
            }
        }
    }

    // ===== Phase B: k=sigmoid(ctx@Wk), v=ctx@Wv, s=k.q, P=s*v -> QS =====
    {
        float ka[2][4][4], va[2][4][4];
#pragma unroll
        for (int m = 0; m < 2; m++)
#pragma unroll
            for (int t = 0; t < 4; t++)
#pragma unroll
                for (int j = 0; j < 4; j++) { ka[m][t][j] = 0.f; va[m][t][j] = 0.f; }

        float k1[8], k2[8], v1[8], v2[8];
        wldg(Wk, 0, warp, lane, k1); wldg(Wk, 0, warp + 8, lane, k2);
        wldg(Wv, 0, warp, lane, v1); wldg(Wv, 0, warp + 8, lane, v2);
        wsts(&sm[OFF_WK], warp, lane, k1); wsts(&sm[OFF_WK], warp + 8, lane, k2);
        wsts(&sm[OFF_WV], warp, lane, v1); wsts(&sm[OFF_WV], warp + 8, lane, v2);
        act_cp(sm, OFF_ACT, ctx, Rbase, 768, 0, tid);
        CP_COMMIT();

#pragma unroll 1
        for (int c = 0; c < 24; c++) {
            const int cb = c & 1;
            if (c + 1 < 24) {
                wldg(Wk, (c + 1) * KC, warp, lane, k1); wldg(Wk, (c + 1) * KC, warp + 8, lane, k2);
                wldg(Wv, (c + 1) * KC, warp, lane, v1); wldg(Wv, (c + 1) * KC, warp + 8, lane, v2);
            }
            CP_WAIT0();
            __syncthreads();
            if (c + 1 < 24) { act_cp(sm, OFF_ACT + (cb ^ 1) * 2304, ctx, Rbase, 768, (c + 1) * KC, tid);
                              CP_COMMIT(); }
            const float* AB = &sm[OFF_ACT + cb * 2304];
            const float* KB = &sm[OFF_WK + cb * 4096];
            const float* VB = &sm[OFF_WV + cb * 4096];
#pragma unroll
            for (int hf = 0; hf < 2; hf++) {
                float4 BtK[4], BtV[4];
#pragma unroll
                for (int t = 0; t < 4; t++) {
                    BtK[t] = *(const float4*)&KB[hf * 2048 + (colgrp * 4 + t) * 128 + lane * 4];
                    BtV[t] = *(const float4*)&VB[hf * 2048 + (colgrp * 4 + t) * 128 + lane * 4];
                }
#pragma unroll
                for (int ks2 = 0; ks2 < 2; ks2++) {
                    const int k = hf * 16 + ks2 * 8 + lm;
                    unsigned a0[2], a1[2], a2[2], a3[2];
#pragma unroll
                    for (int m = 0; m < 2; m++) {
                        const float* Ap = &AB[(band * 32 + m * 16 + l4) * LDA + k];
                        a0[m] = tf32_bits(Ap[0]);       a1[m] = tf32_bits(Ap[8 * LDA]);
                        a2[m] = tf32_bits(Ap[4]);       a3[m] = tf32_bits(Ap[8 * LDA + 4]);
                    }
#pragma unroll
                    for (int t = 0; t < 4; t++) {
                        unsigned b0 = __float_as_uint(ks2 ? BtK[t].z : BtK[t].x);
                        unsigned b1 = __float_as_uint(ks2 ? BtK[t].w : BtK[t].y);
                        mma8(ka[0][t], a0[0], a1[0], a2[0], a3[0], b0, b1);
                        mma8(ka[1][t], a0[1], a1[1], a2[1], a3[1], b0, b1);
                        b0 = __float_as_uint(ks2 ? BtV[t].z : BtV[t].x);
                        b1 = __float_as_uint(ks2 ? BtV[t].w : BtV[t].y);
                        mma8(va[0][t], a0[0], a1[0], a2[0], a3[0], b0, b1);
                        mma8(va[1][t], a0[1], a1[1], a2[1], a3[1], b0, b1);
                    }
                }
            }
            if (c + 1 < 24) {
                wsts(&sm[OFF_WK + (cb ^ 1) * 4096], warp, lane, k1);
                wsts(&sm[OFF_WK + (cb ^ 1) * 4096], warp + 8, lane, k2);
                wsts(&sm[OFF_WV + (cb ^ 1) * 4096], warp, lane, v1);
                wsts(&sm[OFF_WV + (cb ^ 1) * 4096], warp + 8, lane, v2);
            }
        }

        // epilogue: s = q . sigmoid(k) per (row, head=colgrp); P = s*v -> QS (tf32)
#pragma unroll
        for (int m = 0; m < 2; m++) {
            float pA = 0.f, pB = 0.f;
#pragma unroll
            for (int t = 0; t < 4; t++) {
                pA += qa[m][t][0] / (1.f + __expf(-ka[m][t][0]));
                pA += qa[m][t][1] / (1.f + __expf(-ka[m][t][1]));
                pB += qa[m][t][2] / (1.f + __expf(-ka[m][t][2]));
                pB += qa[m][t][3] / (1.f + __expf(-ka[m][t][3]));
            }
            pA += __shfl_xor_sync(0xffffffffu, pA, 1);
            pA += __shfl_xor_sync(0xffffffffu, pA, 2);
            pB += __shfl_xor_sync(0xffffffffu, pB, 1);
            pB += __shfl_xor_sync(0xffffffffu, pB, 2);
            const int rA = band * 32 + m * 16 + l4;
#pragma unroll
            for (int t = 0; t < 4; t++) {
                const int col = colgrp * 32 + t * 8 + 2 * lm;
                *(float2*)&sm[OFF_QS + rA * LDP + col] =
                    make_float2(tf32f(pA * va[m][t][0]), tf32f(pA * va[m][t][1]));
                *(float2*)&sm[OFF_QS + (rA + 8) * LDP + col] =
                    make_float2(tf32f(pB * va[m][t][2]), tf32f(pB * va[m][t][3]));
            }
        }
    }

    // ===== Phase C: y = P @ Wo + bo; fused RMSNorm; y lives in registers =====
    float facc[2][16][4];
#pragma unroll
    for (int m = 0; m < 2; m++)
#pragma unroll
        for (int t = 0; t < 16; t++)
#pragma unroll
            for (int j = 0; j < 4; j++) facc[m][t][j] = 0.f;

#pragma unroll 1
    for (int c = 0; c < 4; c++) {
        __syncthreads();   // prior phase/chunk reads of region0 + P writes visible
        // stage Wo chunk c, frag-major: WF[T 0..63][lane][4] halves at +0 / +8192
#pragma unroll
        for (int gp = 0; gp < 2; gp++) {
            float wr[4][8];
#pragma unroll
            for (int tt = 0; tt < 4; tt++) {
                const int T = warp * 8 + gp * 4 + tt;
                const float* p = Wo + (size_t)(c * 32 + lm) * 512 + T * 8 + l4;
#pragma unroll
                for (int j = 0; j < 4; j++) {
                    wr[tt][j]     = __ldg(p + j * 4 * 512);
                    wr[tt][4 + j] = __ldg(p + (16 + j * 4) * 512);
                }
            }
#pragma unroll
            for (int tt = 0; tt < 4; tt++) {
                const int T = warp * 8 + gp * 4 + tt;
                float4 a4 = make_float4(tf32f(wr[tt][0]), tf32f(wr[tt][1]),
                                        tf32f(wr[tt][2]), tf32f(wr[tt][3]));
                float4 b4 = make_float4(tf32f(wr[tt][4]), tf32f(wr[tt][5]),
                                        tf32f(wr[tt][6]), tf32f(wr[tt][7]));
                *(float4*)&sm[OFF_WO + T * 128 + lane * 4] = a4;
                *(float4*)&sm[OFF_WO + 8192 + T * 128 + lane * 4] = b4;
            }
        }
        __syncthreads();

#pragma unroll
        for (int hf = 0; hf < 2; hf++) {
            unsigned aa[2][2][4];   // [ks2][m]
#pragma unroll
            for (int ks2 = 0; ks2 < 2; ks2++) {
                const int k = c * 32 + hf * 16 + ks2 * 8 + lm;
#pragma unroll
                for (int m = 0; m < 2; m++) {
                    const float* Pp = &sm[OFF_QS + (band * 32 + m * 16 + l4) * LDP + k];
                    aa[ks2][m][0] = __float_as_uint(Pp[0]);
                    aa[ks2][m][1] = __float_as_uint(Pp[8 * LDP]);
                    aa[ks2][m][2] = __float_as_uint(Pp[4]);
                    aa[ks2][m][3] = __float_as_uint(Pp[8 * LDP + 4]);
                }
            }
#pragma unroll
            for (int t = 0; t < 16; t++) {
                const float4 Bt = *(const float4*)&sm[OFF_WO + hf * 8192 + (colgrp * 16 + t) * 128 + lane * 4];
#pragma unroll
                for (int ks2 = 0; ks2 < 2; ks2++) {
                    const unsigned b0 = __float_as_uint(ks2 ? Bt.z : Bt.x);
                    const unsigned b1 = __float_as_uint(ks2 ? Bt.w : Bt.y);
                    mma8(facc[0][t], aa[ks2][0][0], aa[ks2][0][1], aa[ks2][0][2], aa[ks2][0][3], b0, b1);
                    mma8(facc[1][t], aa[ks2][1][0], aa[ks2][1][1], aa[ks2][1][2], aa[ks2][1][3], b0, b1);
                }
            }
        }
    }

    // epilogue: +bo, row sumsq -> norm -> scale by rsc*g, single STG
    float ssA[2] = {0.f, 0.f}, ssB[2] = {0.f, 0.f};
#pragma unroll
    for (int m = 0; m < 2; m++)
#pragma unroll
        for (int t = 0; t < 16; t++) {
            const int col = colgrp * 128 + t * 8 + 2 * lm;
            const float2 b2 = *(const float2*)&sm[OFF_BO + col];
            facc[m][t][0] += b2.x; facc[m][t][1] += b2.y;
            facc[m][t][2] += b2.x; facc[m][t][3] += b2.y;
            ssA[m] += facc[m][t][0] * facc[m][t][0] + facc[m][t][1] * facc[m][t][1];
            ssB[m] += facc[m][t][2] * facc[m][t][2] + facc[m][t][3] * facc[m][t][3];
        }
#pragma unroll
    for (int m = 0; m < 2; m++) {
        ssA[m] += __shfl_xor_sync(0xffffffffu, ssA[m], 1);
        ssA[m] += __shfl_xor_sync(0xffffffffu, ssA[m], 2);
        ssB[m] += __shfl_xor_sync(0xffffffffu, ssB[m], 1);
        ssB[m] += __shfl_xor_sync(0xffffffffu, ssB[m], 2);
        if (lm == 0) {
            atomicAdd(&sm[OFF_N2 + band * 32 + m * 16 + l4], ssA[m]);
            atomicAdd(&sm[OFF_N2 + band * 32 + m * 16 + l4 + 8], ssB[m]);
        }
    }
    __syncthreads();
    if (tid < 64)
        sm[OFF_RS + tid] = 22.627416997969522f / fmaxf(sqrtf(sm[OFF_N2 + tid]), 1e-12f);
    __syncthreads();

#pragma unroll
    for (int m = 0; m < 2; m++) {
        const int rA = band * 32 + m * 16 + l4;
        const float cA = sm[OFF_RS + rA], cB = sm[OFF_RS + rA + 8];
#pragma unroll
        for (int t = 0; t < 16; t++) {
            const int col = colgrp * 128 + t * 8 + 2 * lm;
            const float2 g2 = *(const float2*)&sm[OFF_G + col];
            *(float2*)&out[(Rbase + rA) * 512 + col] =
                make_float2(facc[m][t][0] * cA * g2.x, facc[m][t][1] * cA * g2.y);
            *(float2*)&out[(Rbase + rA + 8) * 512 + col] =
                make_float2(facc[m][t][2] * cB * g2.x, facc[m][t][3] * cB * g2.y);
        }
    }
}

extern "C" void kernel_launch(void* const* d_in, const int* in_sizes, int n_in,
                              void* d_out, int out_size)
{
    const float* x   = (const float*)d_in[0];
    const float* ctx = (const float*)d_in[1];
    const float* Wq  = (const float*)d_in[2];
    const float* Wk  = (const float*)d_in[3];
    const float* Wv  = (const float*)d_in[4];
    const float* Wo  = (const float*)d_in[5];
    const float* bo  = (const float*)d_in[6];
    const float* g   = (const float*)d_in[7];
    float* out = (float*)d_out;

    const int B = in_sizes[0] / 512;   // 65536
    const size_t SMEM = (size_t)SMEM_FLOATS * sizeof(float);

    cudaFuncSetAttribute(lca_tc, cudaFuncAttributeMaxDynamicSharedMemorySize, (int)SMEM);
    lca_tc<<<B / ROWS, THREADS, SMEM>>>(x, ctx, Wq, Wk, Wv, Wo, bo, g, out);
}

// round 4
// speedup vs baseline: 1.5127x; 1.5127x over previous
#include <cuda_runtime.h>
#include <math.h>

#define THREADS 256
#define ROWS 128
#define LDA 36       // activation smem row stride (32+4): conflict-free frag LDS
#define LDP 132      // P / q smem row stride (128+4)

// smem float offsets
#define OFF_P   0        // 128*132 = 16896 (q then P, persistent)
#define OFF_ACT 16896    // 2 x 128*36 = 9216
#define OFF_WK  26112    // 2 x 4096 = 8192
#define OFF_WV  34304    // 2 x 4096 = 8192 (ends 42496)
#define OFF_WO  16896    // phase C: 2 x 16384 = 32768 (overlays ACT/WK/WV, ends 49664)
#define OFF_BO  49664    // 512
#define OFF_G   50176    // 512
#define OFF_N2  50688    // 64
#define OFF_RS  50752    // 64
#define SMEM_FLOATS 50816   // 203264 bytes

// pre-converted frag-major tf32 weights
__device__ float WqF[16 * 4096];
__device__ float WkF[24 * 4096];
__device__ float WvF[24 * 4096];
__device__ float WoF[4 * 16384];

__device__ __forceinline__ unsigned tf32_bits(float x) {
    unsigned u; asm("cvt.rna.tf32.f32 %0, %1;" : "=r"(u) : "f"(x)); return u;
}
__device__ __forceinline__ float tf32f(float x) { return __uint_as_float(tf32_bits(x)); }

__device__ __forceinline__ void mma8(float* d, unsigned a0, unsigned a1, unsigned a2, unsigned a3,
                                     unsigned b0, unsigned b1) {
    asm volatile(
        "mma.sync.aligned.m16n8k8.row.col.f32.tf32.tf32.f32 "
        "{%0,%1,%2,%3},{%4,%5,%6,%7},{%8,%9},{%0,%1,%2,%3};"
        : "+f"(d[0]), "+f"(d[1]), "+f"(d[2]), "+f"(d[3])
        : "r"(a0), "r"(a1), "r"(a2), "r"(a3), "r"(b0), "r"(b1));
}

#define CP_COMMIT() asm volatile("cp.async.commit_group;")
#define CP_WAIT0()  asm volatile("cp.async.wait_group 0;")

__device__ __forceinline__ void cp16(float* smdst, const float* gsrc) {
    unsigned sa = (unsigned)__cvta_generic_to_shared(smdst);
    asm volatile("cp.async.cg.shared.global [%0], [%1], 16;" :: "r"(sa), "l"(gsrc));
}

// activations: 128 rows x 32 cols -> smem [r*LDA + c]
__device__ __forceinline__ void act_cp(float* sm, int dstOff, const float* A,
                                       size_t rowBase, int gld, int kb, int tid) {
#pragma unroll
    for (int i = 0; i < 4; i++) {
        const int idx = tid + THREADS * i;          // 0..1023
        const int r = idx >> 3, q = (idx & 7) * 4;
        cp16(&sm[dstOff + r * LDA + q], A + (rowBase + r) * (size_t)gld + kb + q);
    }
}

// contiguous weight chunk copy (nfloats multiple of 1024)
template <int NF>
__device__ __forceinline__ void w_cp(float* sm, int dstOff, const float* gsrc, int tid) {
#pragma unroll
    for (int i = tid * 4; i < NF; i += THREADS * 4)
        cp16(&sm[dstOff + i], gsrc + i);
}

// ---------------- prep: fp32 row-major weights -> frag-major tf32 ----------------
// proj (W[K,128]): chunk c of 32 k: block[h][T(16)][lane][j] = W[(c*32+h*16+lm+4j)*128 + T*8+l4]
// Wo  (W[128,512]): chunk c: block[h][T(64)][lane][j] = Wo[(c*32+h*16+lm+4j)*512 + T*8+l4]
__global__ void __launch_bounds__(256)
lca_prep(const float* __restrict__ Wq, const float* __restrict__ Wk,
         const float* __restrict__ Wv, const float* __restrict__ Wo)
{
    const int idx = blockIdx.x * 256 + threadIdx.x;
    if (idx < 65536) {                       // WqF
        int i = idx;
        int c = i >> 12, r = i & 4095, h = r >> 11; r &= 2047;
        int T = r >> 7, lane = (r >> 2) & 31, j = r & 3;
        int l4 = lane >> 2, lm = lane & 3;
        int k = c * 32 + h * 16 + lm + 4 * j;
        WqF[i] = tf32f(Wq[k * 128 + T * 8 + l4]);
    } else if (idx < 65536 + 98304) {        // WkF
        int i = idx - 65536;
        int c = i >> 12, r = i & 4095, h = r >> 11; r &= 2047;
        int T = r >> 7, lane = (r >> 2) & 31, j = r & 3;
        int l4 = lane >> 2, lm = lane & 3;
        int k = c * 32 + h * 16 + lm + 4 * j;
        WkF[i] = tf32f(Wk[k * 128 + T * 8 + l4]);
    } else if (idx < 65536 + 2 * 98304) {    // WvF
        int i = idx - 65536 - 98304;
        int c = i >> 12, r = i & 4095, h = r >> 11; r &= 2047;
        int T = r >> 7, lane = (r >> 2) & 31, j = r & 3;
        int l4 = lane >> 2, lm = lane & 3;
        int k = c * 32 + h * 16 + lm + 4 * j;
        WvF[i] = tf32f(Wv[k * 128 + T * 8 + l4]);
    } else {                                 // WoF
        int i = idx - 65536 - 2 * 98304;
        int c = i >> 14, r = i & 16383, h = r >> 13; r &= 8191;
        int T = r >> 7, lane = (r >> 2) & 31, j = r & 3;
        int l4 = lane >> 2, lm = lane & 3;
        int k = c * 32 + h * 16 + lm + 4 * j;
        WoF[i] = tf32f(Wo[k * 512 + T * 8 + l4]);
    }
}

// ---------------------------------- main ----------------------------------
__global__ void __launch_bounds__(THREADS, 1)
lca_tc(const float* __restrict__ x, const float* __restrict__ ctx,
       const float* __restrict__ bo, const float* __restrict__ g,
       float* __restrict__ out)
{
    extern __shared__ float sm[];
    const int tid  = threadIdx.x;
    const int lane = tid & 31;
    const int warp = tid >> 5;
    const int l4   = lane >> 2;
    const int lm   = lane & 3;
    const int band = warp >> 1;     // phases A/B: 4 bands x 32 rows
    const int cg   = warp & 1;      //             2 colgrps x 64 cols
    const int band2 = warp >> 2;    // phase C: 2 bands x 32 rows (per 64-row subpass)
    const int cg2   = warp & 3;     //          4 colgrps x 128 cols
    const size_t Rbase = (size_t)blockIdx.x * ROWS;

    for (int i = tid; i < 512; i += THREADS) {
        sm[OFF_BO + i] = __ldg(&bo[i]);
        sm[OFF_G + i]  = __ldg(&g[i]);
    }
    if (tid < 64) sm[OFF_N2 + tid] = 0.f;

    // ======================= Phase A: q = x @ Wq =======================
    {
        float qa[2][8][4];
#pragma unroll
        for (int m = 0; m < 2; m++)
#pragma unroll
            for (int t = 0; t < 8; t++)
#pragma unroll
                for (int j = 0; j < 4; j++) qa[m][t][j] = 0.f;

        act_cp(sm, OFF_ACT, x, Rbase, 512, 0, tid);
        w_cp<4096>(sm, OFF_WK, WqF, tid);
        CP_COMMIT();

#pragma unroll 1
        for (int c = 0; c < 16; c++) {
            const int cb = c & 1;
            CP_WAIT0();
            __syncthreads();
            if (c + 1 < 16) {
                act_cp(sm, OFF_ACT + (cb ^ 1) * 4608, x, Rbase, 512, (c + 1) * 32, tid);
                w_cp<4096>(sm, OFF_WK + (cb ^ 1) * 4096, WqF + (c + 1) * 4096, tid);
                CP_COMMIT();
            }
            const float* AB = &sm[OFF_ACT + cb * 4608];
            const float* WB = &sm[OFF_WK + cb * 4096];
#pragma unroll
            for (int hf = 0; hf < 2; hf++) {
                unsigned aa[2][2][4];
#pragma unroll
                for (int ks2 = 0; ks2 < 2; ks2++) {
                    const int k = hf * 16 + ks2 * 8 + lm;
#pragma unroll
                    for (int m = 0; m < 2; m++) {
                        const float* Ap = &AB[(band * 32 + m * 16 + l4) * LDA + k];
                        aa[ks2][m][0] = tf32_bits(Ap[0]);
                        aa[ks2][m][1] = tf32_bits(Ap[8 * LDA]);
                        aa[ks2][m][2] = tf32_bits(Ap[4]);
                        aa[ks2][m][3] = tf32_bits(Ap[8 * LDA + 4]);
                    }
                }
#pragma unroll
                for (int t = 0; t < 8; t++) {
                    const float4 Bt = *(const float4*)&WB[hf * 2048 + (cg * 8 + t) * 128 + lane * 4];
#pragma unroll
                    for (int ks2 = 0; ks2 < 2; ks2++) {
                        const unsigned b0 = __float_as_uint(ks2 ? Bt.z : Bt.x);
                        const unsigned b1 = __float_as_uint(ks2 ? Bt.w : Bt.y);
                        mma8(qa[0][t], aa[ks2][0][0], aa[ks2][0][1], aa[ks2][0][2], aa[ks2][0][3], b0, b1);
                        mma8(qa[1][t], aa[ks2][1][0], aa[ks2][1][1], aa[ks2][1][2], aa[ks2][1][3], b0, b1);
                    }
                }
            }
        }
        // write raw q to P region
#pragma unroll
        for (int m = 0; m < 2; m++) {
            const int rA = band * 32 + m * 16 + l4;
#pragma unroll
            for (int t = 0; t < 8; t++) {
                const int col = (cg * 8 + t) * 8 + 2 * lm;
                *(float2*)&sm[OFF_P + rA * LDP + col]       = make_float2(qa[m][t][0], qa[m][t][1]);
                *(float2*)&sm[OFF_P + (rA + 8) * LDP + col] = make_float2(qa[m][t][2], qa[m][t][3]);
            }
        }
    }
    __syncthreads();

    // phase B prologue loads (overlap with softmax)
    act_cp(sm, OFF_ACT, ctx, Rbase, 768, 0, tid);
    w_cp<4096>(sm, OFF_WK, WkF, tid);
    w_cp<4096>(sm, OFF_WV, WvF, tid);
    CP_COMMIT();

    // softmax per (row, head), *scale, in smem
    for (int task = tid; task < ROWS * 4; task += THREADS) {
        const int r = task >> 2, h = task & 3;
        float* qp = &sm[OFF_P + r * LDP + h * 32];
        float mx = qp[0];
#pragma unroll
        for (int i = 1; i < 32; i++) mx = fmaxf(mx, qp[i]);
        float s = 0.f;
#pragma unroll
        for (int i = 0; i < 32; i++) s += __expf(qp[i] - mx);
        const float inv = 0.17677669529663687f / s;   // 32^-0.5 / sum
#pragma unroll
        for (int i = 0; i < 32; i++) qp[i] = __expf(qp[i] - mx) * inv;
    }

    // ===== Phase B: k=sigmoid(ctx@Wk), v=ctx@Wv, s=q.k, P=s*v =====
    {
        float ka[2][8][4], va[2][8][4];
#pragma unroll
        for (int m = 0; m < 2; m++)
#pragma unroll
            for (int t = 0; t < 8; t++)
#pragma unroll
                for (int j = 0; j < 4; j++) { ka[m][t][j] = 0.f; va[m][t][j] = 0.f; }

#pragma unroll 1
        for (int c = 0; c < 24; c++) {
            const int cb = c & 1;
            CP_WAIT0();
            __syncthreads();
            if (c + 1 < 24) {
                act_cp(sm, OFF_ACT + (cb ^ 1) * 4608, ctx, Rbase, 768, (c + 1) * 32, tid);
                w_cp<4096>(sm, OFF_WK + (cb ^ 1) * 4096, WkF + (c + 1) * 4096, tid);
                w_cp<4096>(sm, OFF_WV + (cb ^ 1) * 4096, WvF + (c + 1) * 4096, tid);
                CP_COMMIT();
            }
            const float* AB = &sm[OFF_ACT + cb * 4608];
            const float* KB = &sm[OFF_WK + cb * 4096];
            const float* VB = &sm[OFF_WV + cb * 4096];
#pragma unroll
            for (int hf = 0; hf < 2; hf++) {
                unsigned aa[2][2][4];
#pragma unroll
                for (int ks2 = 0; ks2 < 2; ks2++) {
                    const int k = hf * 16 + ks2 * 8 + lm;
#pragma unroll
                    for (int m = 0; m < 2; m++) {
                        const float* Ap = &AB[(band * 32 + m * 16 + l4) * LDA + k];
                        aa[ks2][m][0] = tf32_bits(Ap[0]);
                        aa[ks2][m][1] = tf32_bits(Ap[8 * LDA]);
                        aa[ks2][m][2] = tf32_bits(Ap[4]);
                        aa[ks2][m][3] = tf32_bits(Ap[8 * LDA + 4]);
                    }
                }
#pragma unroll
                for (int t = 0; t < 8; t++) {
                    const int toff = hf * 2048 + (cg * 8 + t) * 128 + lane * 4;
                    const float4 BtK = *(const float4*)&KB[toff];
                    const float4 BtV = *(const float4*)&VB[toff];
#pragma unroll
                    for (int ks2 = 0; ks2 < 2; ks2++) {
                        unsigned b0 = __float_as_uint(ks2 ? BtK.z : BtK.x);
                        unsigned b1 = __float_as_uint(ks2 ? BtK.w : BtK.y);
                        mma8(ka[0][t], aa[ks2][0][0], aa[ks2][0][1], aa[ks2][0][2], aa[ks2][0][3], b0, b1);
                        mma8(ka[1][t], aa[ks2][1][0], aa[ks2][1][1], aa[ks2][1][2], aa[ks2][1][3], b0, b1);
                        b0 = __float_as_uint(ks2 ? BtV.z : BtV.x);
                        b1 = __float_as_uint(ks2 ? BtV.w : BtV.y);
                        mma8(va[0][t], aa[ks2][0][0], aa[ks2][0][1], aa[ks2][0][2], aa[ks2][0][3], b0, b1);
                        mma8(va[1][t], aa[ks2][1][0], aa[ks2][1][1], aa[ks2][1][2], aa[ks2][1][3], b0, b1);
                    }
                }
            }
        }

        // all compute done; start Wo chunk0 transfer before epilogue math
        __syncthreads();
        w_cp<16384>(sm, OFF_WO, WoF, tid);
        CP_COMMIT();

        // epilogue: s = q . sigmoid(k) per (row, head); P = s*v (tf32)
#pragma unroll
        for (int m = 0; m < 2; m++) {
            const int rA = band * 32 + m * 16 + l4;
            float d[2][2] = {{0.f, 0.f}, {0.f, 0.f}};
#pragma unroll
            for (int t = 0; t < 8; t++) {
                const int hh = t >> 2;
                const int col = (cg * 8 + t) * 8 + 2 * lm;
                const float2 q1 = *(const float2*)&sm[OFF_P + rA * LDP + col];
                const float2 q2 = *(const float2*)&sm[OFF_P + (rA + 8) * LDP + col];
                d[0][hh] += q1.x / (1.f + __expf(-ka[m][t][0])) + q1.y / (1.f + __expf(-ka[m][t][1]));
                d[1][hh] += q2.x / (1.f + __expf(-ka[m][t][2])) + q2.y / (1.f + __expf(-ka[m][t][3]));
            }
#pragma unroll
            for (int rh = 0; rh < 2; rh++)
#pragma unroll
                for (int hh = 0; hh < 2; hh++) {
                    d[rh][hh] += __shfl_xor_sync(0xffffffffu, d[rh][hh], 1);
                    d[rh][hh] += __shfl_xor_sync(0xffffffffu, d[rh][hh], 2);
                }
#pragma unroll
            for (int t = 0; t < 8; t++) {
                const int hh = t >> 2;
                const int col = (cg * 8 + t) * 8 + 2 * lm;
                *(float2*)&sm[OFF_P + rA * LDP + col] =
                    make_float2(tf32f(d[0][hh] * va[m][t][0]), tf32f(d[0][hh] * va[m][t][1]));
                *(float2*)&sm[OFF_P + (rA + 8) * LDP + col] =
                    make_float2(tf32f(d[1][hh] * va[m][t][2]), tf32f(d[1][hh] * va[m][t][3]));
            }
        }
    }

    // ===== Phase C: y = P @ Wo + bo, fused RMSNorm; 2 subpasses of 64 rows =====
#pragma unroll 1
    for (int sp = 0; sp < 2; sp++) {
        float facc[2][16][4];
#pragma unroll
        for (int m = 0; m < 2; m++)
#pragma unroll
            for (int t = 0; t < 16; t++)
#pragma unroll
                for (int j = 0; j < 4; j++) facc[m][t][j] = 0.f;

#pragma unroll 1
        for (int c = 0; c < 4; c++) {
            const int cb = c & 1;
            CP_WAIT0();
            __syncthreads();
            if (!(sp == 1 && c == 3)) {
                const int nc = (c + 1) & 3;
                w_cp<16384>(sm, OFF_WO + (cb ^ 1) * 16384, WoF + nc * 16384, tid);
                CP_COMMIT();
            }
            const float* WOB = &sm[OFF_WO + cb * 16384];
#pragma unroll
            for (int hf = 0; hf < 2; hf++) {
                unsigned aa[2][2][4];
#pragma unroll
                for (int ks2 = 0; ks2 < 2; ks2++) {
                    const int k = c * 32 + hf * 16 + ks2 * 8 + lm;
#pragma unroll
                    for (int m = 0; m < 2; m++) {
                        const float* Pp = &sm[OFF_P + (sp * 64 + band2 * 32 + m * 16 + l4) * LDP + k];
                        aa[ks2][m][0] = __float_as_uint(Pp[0]);
                        aa[ks2][m][1] = __float_as_uint(Pp[8 * LDP]);
                        aa[ks2][m][2] = __float_as_uint(Pp[4]);
                        aa[ks2][m][3] = __float_as_uint(Pp[8 * LDP + 4]);
                    }
                }
#pragma unroll
                for (int t = 0; t < 16; t++) {
                    const float4 Bt = *(const float4*)&WOB[hf * 8192 + (cg2 * 16 + t) * 128 + lane * 4];
#pragma unroll
                    for (int ks2 = 0; ks2 < 2; ks2++) {
                        const unsigned b0 = __float_as_uint(ks2 ? Bt.z : Bt.x);
                        const unsigned b1 = __float_as_uint(ks2 ? Bt.w : Bt.y);
                        mma8(facc[0][t], aa[ks2][0][0], aa[ks2][0][1], aa[ks2][0][2], aa[ks2][0][3], b0, b1);
                        mma8(facc[1][t], aa[ks2][1][0], aa[ks2][1][1], aa[ks2][1][2], aa[ks2][1][3], b0, b1);
                    }
                }
            }
        }

        // epilogue: +bo, row sumsq, norm, scale, store
        float ssA[2] = {0.f, 0.f}, ssB[2] = {0.f, 0.f};
#pragma unroll
        for (int m = 0; m < 2; m++)
#pragma unroll
            for (int t = 0; t < 16; t++) {
                const int col = cg2 * 128 + t * 8 + 2 * lm;
                const float2 b2 = *(const float2*)&sm[OFF_BO + col];
                facc[m][t][0] += b2.x; facc[m][t][1] += b2.y;
                facc[m][t][2] += b2.x; facc[m][t][3] += b2.y;
                ssA[m] += facc[m][t][0] * facc[m][t][0] + facc[m][t][1] * facc[m][t][1];
                ssB[m] += facc[m][t][2] * facc[m][t][2] + facc[m][t][3] * facc[m][t][3];
            }
#pragma unroll
        for (int m = 0; m < 2; m++) {
            ssA[m] += __shfl_xor_sync(0xffffffffu, ssA[m], 1);
            ssA[m] += __shfl_xor_sync(0xffffffffu, ssA[m], 2);
            ssB[m] += __shfl_xor_sync(0xffffffffu, ssB[m], 1);
            ssB[m] += __shfl_xor_sync(0xffffffffu, ssB[m], 2);
            if (lm == 0) {
                atomicAdd(&sm[OFF_N2 + band2 * 32 + m * 16 + l4], ssA[m]);
                atomicAdd(&sm[OFF_N2 + band2 * 32 + m * 16 + l4 + 8], ssB[m]);
            }
        }
        __syncthreads();
        if (tid < 64) {
            sm[OFF_RS + tid] = 22.627416997969522f / fmaxf(sqrtf(sm[OFF_N2 + tid]), 1e-12f);
            sm[OFF_N2 + tid] = 0.f;   // ready for next subpass
        }
        __syncthreads();

#pragma unroll
        for (int m = 0; m < 2; m++) {
            const int rloc = band2 * 32 + m * 16 + l4;
            const float cA = sm[OFF_RS + rloc], cB = sm[OFF_RS + rloc + 8];
            const size_t gr = (Rbase + sp * 64 + rloc) * 512;
#pragma unroll
            for (int t = 0; t < 16; t++) {
                const int col = cg2 * 128 + t * 8 + 2 * lm;
                const float2 g2 = *(const float2*)&sm[OFF_G + col];
                *(float2*)&out[gr + col] =
                    make_float2(facc[m][t][0] * cA * g2.x, facc[m][t][1] * cA * g2.y);
                *(float2*)&out[gr + 8 * 512 + col] =
                    make_float2(facc[m][t][2] * cB * g2.x, facc[m][t][3] * cB * g2.y);
            }
        }
    }
}

extern "C" void kernel_launch(void* const* d_in, const int* in_sizes, int n_in,
                              void* d_out, int out_size)
{
    const float* x   = (const float*)d_in[0];
    const float* ctx = (const float*)d_in[1];
    const float* Wq  = (const float*)d_in[2];
    const float* Wk  = (const float*)d_in[3];
    const float* Wv  = (const float*)d_in[4];
    const float* Wo  = (const float*)d_in[5];
    const float* bo  = (const float*)d_in[6];
    const float* g   = (const float*)d_in[7];
    float* out = (float*)d_out;

    const int B = in_sizes[0] / 512;   // 65536
    const size_t SMEM = (size_t)SMEM_FLOATS * sizeof(float);

    lca_prep<<<1280, 256>>>(Wq, Wk, Wv, Wo);

    cudaFuncSetAttribute(lca_tc, cudaFuncAttributeMaxDynamicSharedMemorySize, (int)SMEM);
    lca_tc<<<B / ROWS, THREADS, SMEM>>>(x, ctx, bo, g, out);
}